// round 13
// baseline (speedup 1.0000x reference)
#include <cuda_runtime.h>

#define NN 1024
#define FF 128
#define ALPHA 0.2f
#define NEGV -9.0e15f

// Scratch (static device globals — no allocation)
__device__ float g_Wh[NN * FF];
__device__ float g_si[NN];
__device__ float g_sj[NN];
__device__ float g_inv[NN];
__device__ float g_att[(size_t)NN * NN];   // UNNORMALIZED exp weights

__device__ __forceinline__ float4 ldcs4(const float4* p) {
#if __CUDA_ARCH__ >= 800
    float4 v;
    asm volatile("ld.global.cs.v4.f32 {%0,%1,%2,%3}, [%4];"
                 : "=f"(v.x), "=f"(v.y), "=f"(v.z), "=f"(v.w) : "l"(p));
    return v;
#else
    return *p;
#endif
}

// ---------------------------------------------------------------------------
// Kernel A (v4): Wh = h @ W + b, fused s_i/s_j.
// 4 rows/block, 256 blocks x 256 threads, 8-way k-split:
//   warp w owns k in [16w, 16w+16); lane owns col quad [4*lane, 4*lane+4).
// Each W LDG.128 feeds 16 FMAs (4 rows x 4 cols) -> W L2 traffic
// 64 MB -> 16 MB (was the binding constraint at the LTS cap).
// ---------------------------------------------------------------------------
__global__ __launch_bounds__(256) void k_wh(const float* __restrict__ h,
                                            const float* __restrict__ W,
                                            const float* __restrict__ b,
                                            const float* __restrict__ aw) {
    int tid = threadIdx.x;
    int warp = tid >> 5, lane = tid & 31;
    int i0 = blockIdx.x * 4;

    __shared__ float hs[4][FF];             // 2 KB
    __shared__ float4 part[8][4][32];       // 16 KB: [kwarp][row][colquad]

    if (tid < 128)                          // 4 rows x 32 float4, coalesced
        ((float4*)hs)[tid] = ((const float4*)(h + (size_t)i0 * FF))[tid];
    __syncthreads();

    const float4* W4 = (const float4*)W;    // [128][32] float4
    float4 a0 = make_float4(0.f, 0.f, 0.f, 0.f);
    float4 a1 = a0, a2 = a0, a3 = a0;
    int k0 = warp * 16;
#pragma unroll
    for (int kk = 0; kk < 16; kk++) {
        int k = k0 + kk;
        float4 w = W4[k * 32 + lane];       // coalesced 512B/warp
        float h0 = hs[0][k], h1 = hs[1][k], h2 = hs[2][k], h3 = hs[3][k];
        a0.x = fmaf(h0, w.x, a0.x); a0.y = fmaf(h0, w.y, a0.y);
        a0.z = fmaf(h0, w.z, a0.z); a0.w = fmaf(h0, w.w, a0.w);
        a1.x = fmaf(h1, w.x, a1.x); a1.y = fmaf(h1, w.y, a1.y);
        a1.z = fmaf(h1, w.z, a1.z); a1.w = fmaf(h1, w.w, a1.w);
        a2.x = fmaf(h2, w.x, a2.x); a2.y = fmaf(h2, w.y, a2.y);
        a2.z = fmaf(h2, w.z, a2.z); a2.w = fmaf(h2, w.w, a2.w);
        a3.x = fmaf(h3, w.x, a3.x); a3.y = fmaf(h3, w.y, a3.y);
        a3.z = fmaf(h3, w.z, a3.z); a3.w = fmaf(h3, w.w, a3.w);
    }
    part[warp][0][lane] = a0;
    part[warp][1][lane] = a1;
    part[warp][2][lane] = a2;
    part[warp][3][lane] = a3;
    __syncthreads();

    if (tid < 128) {                        // warp r handles row i0+r
        int r = tid >> 5, l = tid & 31;
        float4 s = part[0][r][l];
#pragma unroll
        for (int w = 1; w < 8; w++) {
            float4 p = part[w][r][l];
            s.x += p.x; s.y += p.y; s.z += p.z; s.w += p.w;
        }
        float4 bb = ((const float4*)b)[l];
        s.x += bb.x; s.y += bb.y; s.z += bb.z; s.w += bb.w;
        ((float4*)(g_Wh + (size_t)(i0 + r) * FF))[l] = s;

        float4 ai = ((const float4*)aw)[l];
        float4 aj = ((const float4*)(aw + FF))[l];
        float pi = fmaf(s.x, ai.x, fmaf(s.y, ai.y, fmaf(s.z, ai.z, s.w * ai.w)));
        float pj = fmaf(s.x, aj.x, fmaf(s.y, aj.y, fmaf(s.z, aj.z, s.w * aj.w)));
#pragma unroll
        for (int o = 16; o; o >>= 1) {
            pi += __shfl_xor_sync(0xffffffffu, pi, o);
            pj += __shfl_xor_sync(0xffffffffu, pj, o);
        }
        if (l == 0) { g_si[i0 + r] = pi; g_sj[i0 + r] = pj; }
    }
}

// ---------------------------------------------------------------------------
// Kernel B (HBM-bound, PROTECTED WIN — byte-identical to R9/R10): per row i,
// fused dual GEMV + leaky-ReLU + mask + softmax (unnormalized + g_inv).
// __launch_bounds__(256,7) -> ALL 1024 blocks resident in ONE wave.
// ---------------------------------------------------------------------------
__global__ __launch_bounds__(256, 7) void k_attn(const float* __restrict__ eh,
                                                 const float* __restrict__ de,
                                                 const int* __restrict__ adj,
                                                 const float* __restrict__ aw,
                                                 const float* __restrict__ ab) {
    int i = blockIdx.x;
    int tid = threadIdx.x;
    int warp = tid >> 5, lane = tid & 31;

    __shared__ float sh[NN];
    __shared__ float red[8];

    float4 ae = ((const float4*)(aw + 2 * FF))[lane];
    float4 ad = ((const float4*)(aw + 3 * FF))[lane];
    float base = g_si[i] + ab[0];

    const float4* pe = (const float4*)(eh + (size_t)i * NN * FF);
    const float4* pd = (const float4*)(de + (size_t)i * NN * FF);

#pragma unroll 2
    for (int j = warp; j < NN; j += 8) {
        float4 x = ldcs4(pe + j * 32 + lane);
        float4 y = ldcs4(pd + j * 32 + lane);
        float p = fmaf(x.x, ae.x, fmaf(x.y, ae.y, fmaf(x.z, ae.z, x.w * ae.w)));
        p = fmaf(y.x, ad.x, fmaf(y.y, ad.y, fmaf(y.z, ad.z, fmaf(y.w, ad.w, p))));
#pragma unroll
        for (int o = 16; o; o >>= 1) p += __shfl_xor_sync(0xffffffffu, p, o);
        if (lane == 0) {
            float v = base + g_sj[j] + p;
            sh[j] = v > 0.f ? v : ALPHA * v;
        }
    }
    __syncthreads();

    int4 a4 = ((const int4*)(adj + (size_t)i * NN))[tid];
    float4 v4 = *((float4*)&sh[tid * 4]);
    v4.x = a4.x > 0 ? v4.x : NEGV;
    v4.y = a4.y > 0 ? v4.y : NEGV;
    v4.z = a4.z > 0 ? v4.z : NEGV;
    v4.w = a4.w > 0 ? v4.w : NEGV;
    float m = fmaxf(fmaxf(v4.x, v4.y), fmaxf(v4.z, v4.w));
#pragma unroll
    for (int o = 16; o; o >>= 1) m = fmaxf(m, __shfl_xor_sync(0xffffffffu, m, o));
    if (lane == 0) red[warp] = m;
    __syncthreads();
    float mm = red[0];
#pragma unroll
    for (int k = 1; k < 8; k++) mm = fmaxf(mm, red[k]);

    float4 e4;
    e4.x = __expf(v4.x - mm);
    e4.y = __expf(v4.y - mm);
    e4.z = __expf(v4.z - mm);
    e4.w = __expf(v4.w - mm);
    ((float4*)(g_att + (size_t)i * NN))[tid] = e4;
    float s = (e4.x + e4.y) + (e4.z + e4.w);
#pragma unroll
    for (int o = 16; o; o >>= 1) s += __shfl_xor_sync(0xffffffffu, s, o);
    __syncthreads();
    if (lane == 0) red[warp] = s;
    __syncthreads();
    if (tid == 0) {
        float tot = red[0];
#pragma unroll
        for (int k = 1; k < 8; k++) tot += red[k];
        g_inv[i] = 1.f / tot;
    }
}

// ---------------------------------------------------------------------------
// Kernel D (v2): out = elu((att*inv) @ Wh).  8 rows/block, 128 blocks x 256.
// Halves Wh L2 traffic vs v1 (128 MB -> 64 MB).  attT (32 KB) and the
// cross-warp reduce buffer (32 KB) have disjoint lifetimes -> ALIASED in
// one 32 KB smem buffer to stay under the 48 KB static limit.
// Inner loop: 2 broadcast LDS.128 + 1 coalesced LDG.128 + 32 FMA per j.
// ---------------------------------------------------------------------------
__global__ __launch_bounds__(256) void k_out(float* __restrict__ out) {
    int tid = threadIdx.x;
    int warp = tid >> 5, lane = tid & 31;
    int i0 = blockIdx.x * 8;

    __shared__ float4 buf[2 * NN];   // 32 KB; phase 1: attLo[j]=buf[j],
                                     // attHi[j]=buf[NN+j]; phase 2: sred

    float iv[8];
    const float* ar[8];
#pragma unroll
    for (int r = 0; r < 8; r++) {
        iv[r] = g_inv[i0 + r];
        ar[r] = g_att + (size_t)(i0 + r) * NN;
    }
#pragma unroll
    for (int q = 0; q < 4; q++) {
        int j = tid + q * 256;
        float4 lo, hi;
        lo.x = ar[0][j] * iv[0];
        lo.y = ar[1][j] * iv[1];
        lo.z = ar[2][j] * iv[2];
        lo.w = ar[3][j] * iv[3];
        hi.x = ar[4][j] * iv[4];
        hi.y = ar[5][j] * iv[5];
        hi.z = ar[6][j] * iv[6];
        hi.w = ar[7][j] * iv[7];
        buf[j] = lo;
        buf[NN + j] = hi;
    }
    __syncthreads();

    float4 c0 = make_float4(0.f, 0.f, 0.f, 0.f);
    float4 c1 = c0, c2 = c0, c3 = c0, c4 = c0, c5 = c0, c6 = c0, c7 = c0;
    const float4* wh4 = (const float4*)g_Wh;
    int jb = warp * 128;
#pragma unroll 2
    for (int jj = 0; jj < 128; jj++) {
        int j = jb + jj;
        float4 aL = buf[j];                         // broadcast
        float4 aH = buf[NN + j];                    // broadcast
        float4 w = wh4[(size_t)j * 32 + lane];      // coalesced 512B/warp
        c0.x = fmaf(aL.x, w.x, c0.x); c0.y = fmaf(aL.x, w.y, c0.y);
        c0.z = fmaf(aL.x, w.z, c0.z); c0.w = fmaf(aL.x, w.w, c0.w);
        c1.x = fmaf(aL.y, w.x, c1.x); c1.y = fmaf(aL.y, w.y, c1.y);
        c1.z = fmaf(aL.y, w.z, c1.z); c1.w = fmaf(aL.y, w.w, c1.w);
        c2.x = fmaf(aL.z, w.x, c2.x); c2.y = fmaf(aL.z, w.y, c2.y);
        c2.z = fmaf(aL.z, w.z, c2.z); c2.w = fmaf(aL.z, w.w, c2.w);
        c3.x = fmaf(aL.w, w.x, c3.x); c3.y = fmaf(aL.w, w.y, c3.y);
        c3.z = fmaf(aL.w, w.z, c3.z); c3.w = fmaf(aL.w, w.w, c3.w);
        c4.x = fmaf(aH.x, w.x, c4.x); c4.y = fmaf(aH.x, w.y, c4.y);
        c4.z = fmaf(aH.x, w.z, c4.z); c4.w = fmaf(aH.x, w.w, c4.w);
        c5.x = fmaf(aH.y, w.x, c5.x); c5.y = fmaf(aH.y, w.y, c5.y);
        c5.z = fmaf(aH.y, w.z, c5.z); c5.w = fmaf(aH.y, w.w, c5.w);
        c6.x = fmaf(aH.z, w.x, c6.x); c6.y = fmaf(aH.z, w.y, c6.y);
        c6.z = fmaf(aH.z, w.z, c6.z); c6.w = fmaf(aH.z, w.w, c6.w);
        c7.x = fmaf(aH.w, w.x, c7.x); c7.y = fmaf(aH.w, w.y, c7.y);
        c7.z = fmaf(aH.w, w.z, c7.z); c7.w = fmaf(aH.w, w.w, c7.w);
    }
    __syncthreads();                 // attT fully consumed; buf becomes sred

    // sred[r][w][lane] = buf[(r*8 + w)*32 + lane]
    buf[(0 * 8 + warp) * 32 + lane] = c0;
    buf[(1 * 8 + warp) * 32 + lane] = c1;
    buf[(2 * 8 + warp) * 32 + lane] = c2;
    buf[(3 * 8 + warp) * 32 + lane] = c3;
    buf[(4 * 8 + warp) * 32 + lane] = c4;
    buf[(5 * 8 + warp) * 32 + lane] = c5;
    buf[(6 * 8 + warp) * 32 + lane] = c6;
    buf[(7 * 8 + warp) * 32 + lane] = c7;
    __syncthreads();

    {
        int r = tid >> 5, l = tid & 31;   // 8 rows x 32 lanes = 256 threads
        float4 s = buf[(r * 8 + 0) * 32 + l];
#pragma unroll
        for (int w = 1; w < 8; w++) {
            float4 o = buf[(r * 8 + w) * 32 + l];
            s.x += o.x; s.y += o.y; s.z += o.z; s.w += o.w;
        }
        float4 res;
        res.x = s.x > 0.f ? s.x : expm1f(s.x);
        res.y = s.y > 0.f ? s.y : expm1f(s.y);
        res.z = s.z > 0.f ? s.z : expm1f(s.z);
        res.w = s.w > 0.f ? s.w : expm1f(s.w);
        ((float4*)(out + (size_t)(i0 + r) * FF))[l] = res;
    }
}

// ---------------------------------------------------------------------------
// Launch.  Inputs: h, e_h, dialogue_embedding, adj, W_w, W_b, a_w, a_b.
// Output: fp32 [1024, 128].
// ---------------------------------------------------------------------------
extern "C" void kernel_launch(void* const* d_in, const int* in_sizes, int n_in,
                              void* d_out, int out_size) {
    const float* h   = (const float*)d_in[0];
    const float* eh  = (const float*)d_in[1];
    const float* de  = (const float*)d_in[2];
    const int*   adj = (const int*)d_in[3];
    const float* Ww  = (const float*)d_in[4];
    const float* Wb  = (const float*)d_in[5];
    const float* aw  = (const float*)d_in[6];
    const float* ab  = (const float*)d_in[7];
    float* out = (float*)d_out;

    k_wh<<<NN / 4, 256>>>(h, Ww, Wb, aw);
    k_attn<<<NN, 256>>>(eh, de, adj, aw, ab);
    k_out<<<NN / 8, 256>>>(out);
}

// round 16
// speedup vs baseline: 1.0742x; 1.0742x over previous
#include <cuda_runtime.h>

#define NN 1024
#define FF 128
#define ALPHA 0.2f
#define NEGV -9.0e15f

// Scratch (static device globals — no allocation)
__device__ float g_Wh[NN * FF];
__device__ float g_si[NN];
__device__ float g_sj[NN];
__device__ float g_inv[NN];
__device__ float g_att[(size_t)NN * NN];   // UNNORMALIZED exp weights

__device__ __forceinline__ float4 ldcs4(const float4* p) {
#if __CUDA_ARCH__ >= 800
    float4 v;
    asm volatile("ld.global.cs.v4.f32 {%0,%1,%2,%3}, [%4];"
                 : "=f"(v.x), "=f"(v.y), "=f"(v.z), "=f"(v.w) : "l"(p));
    return v;
#else
    return *p;
#endif
}

// ---------------------------------------------------------------------------
// Kernel A (v4, MEASURED 8.6us): Wh = h @ W + b, fused s_i/s_j.
// 4 rows/block, 256 blocks x 256 threads, 8-way k-split:
//   warp w owns k in [16w, 16w+16); lane owns col quad [4*lane, 4*lane+4).
// Each W LDG.128 feeds 16 FMAs -> W L2 traffic 16 MB.
// ---------------------------------------------------------------------------
__global__ __launch_bounds__(256) void k_wh(const float* __restrict__ h,
                                            const float* __restrict__ W,
                                            const float* __restrict__ b,
                                            const float* __restrict__ aw) {
    int tid = threadIdx.x;
    int warp = tid >> 5, lane = tid & 31;
    int i0 = blockIdx.x * 4;

    __shared__ float hs[4][FF];             // 2 KB
    __shared__ float4 part[8][4][32];       // 16 KB: [kwarp][row][colquad]

    if (tid < 128)                          // 4 rows x 32 float4, coalesced
        ((float4*)hs)[tid] = ((const float4*)(h + (size_t)i0 * FF))[tid];
    __syncthreads();

    const float4* W4 = (const float4*)W;    // [128][32] float4
    float4 a0 = make_float4(0.f, 0.f, 0.f, 0.f);
    float4 a1 = a0, a2 = a0, a3 = a0;
    int k0 = warp * 16;
#pragma unroll
    for (int kk = 0; kk < 16; kk++) {
        int k = k0 + kk;
        float4 w = W4[k * 32 + lane];       // coalesced 512B/warp
        float h0 = hs[0][k], h1 = hs[1][k], h2 = hs[2][k], h3 = hs[3][k];
        a0.x = fmaf(h0, w.x, a0.x); a0.y = fmaf(h0, w.y, a0.y);
        a0.z = fmaf(h0, w.z, a0.z); a0.w = fmaf(h0, w.w, a0.w);
        a1.x = fmaf(h1, w.x, a1.x); a1.y = fmaf(h1, w.y, a1.y);
        a1.z = fmaf(h1, w.z, a1.z); a1.w = fmaf(h1, w.w, a1.w);
        a2.x = fmaf(h2, w.x, a2.x); a2.y = fmaf(h2, w.y, a2.y);
        a2.z = fmaf(h2, w.z, a2.z); a2.w = fmaf(h2, w.w, a2.w);
        a3.x = fmaf(h3, w.x, a3.x); a3.y = fmaf(h3, w.y, a3.y);
        a3.z = fmaf(h3, w.z, a3.z); a3.w = fmaf(h3, w.w, a3.w);
    }
    part[warp][0][lane] = a0;
    part[warp][1][lane] = a1;
    part[warp][2][lane] = a2;
    part[warp][3][lane] = a3;
    __syncthreads();

    if (tid < 128) {                        // warp r handles row i0+r
        int r = tid >> 5, l = tid & 31;
        float4 s = part[0][r][l];
#pragma unroll
        for (int w = 1; w < 8; w++) {
            float4 p = part[w][r][l];
            s.x += p.x; s.y += p.y; s.z += p.z; s.w += p.w;
        }
        float4 bb = ((const float4*)b)[l];
        s.x += bb.x; s.y += bb.y; s.z += bb.z; s.w += bb.w;
        ((float4*)(g_Wh + (size_t)(i0 + r) * FF))[l] = s;

        float4 ai = ((const float4*)aw)[l];
        float4 aj = ((const float4*)(aw + FF))[l];
        float pi = fmaf(s.x, ai.x, fmaf(s.y, ai.y, fmaf(s.z, ai.z, s.w * ai.w)));
        float pj = fmaf(s.x, aj.x, fmaf(s.y, aj.y, fmaf(s.z, aj.z, s.w * aj.w)));
#pragma unroll
        for (int o = 16; o; o >>= 1) {
            pi += __shfl_xor_sync(0xffffffffu, pi, o);
            pj += __shfl_xor_sync(0xffffffffu, pj, o);
        }
        if (l == 0) { g_si[i0 + r] = pi; g_sj[i0 + r] = pj; }
    }
}

// ---------------------------------------------------------------------------
// Kernel B (HBM-bound, PROTECTED WIN — byte-identical to R9/R10): per row i,
// fused dual GEMV + leaky-ReLU + mask + softmax (unnormalized + g_inv).
// __launch_bounds__(256,7) -> ALL 1024 blocks resident in ONE wave.
// ---------------------------------------------------------------------------
__global__ __launch_bounds__(256, 7) void k_attn(const float* __restrict__ eh,
                                                 const float* __restrict__ de,
                                                 const int* __restrict__ adj,
                                                 const float* __restrict__ aw,
                                                 const float* __restrict__ ab) {
    int i = blockIdx.x;
    int tid = threadIdx.x;
    int warp = tid >> 5, lane = tid & 31;

    __shared__ float sh[NN];
    __shared__ float red[8];

    float4 ae = ((const float4*)(aw + 2 * FF))[lane];
    float4 ad = ((const float4*)(aw + 3 * FF))[lane];
    float base = g_si[i] + ab[0];

    const float4* pe = (const float4*)(eh + (size_t)i * NN * FF);
    const float4* pd = (const float4*)(de + (size_t)i * NN * FF);

#pragma unroll 2
    for (int j = warp; j < NN; j += 8) {
        float4 x = ldcs4(pe + j * 32 + lane);
        float4 y = ldcs4(pd + j * 32 + lane);
        float p = fmaf(x.x, ae.x, fmaf(x.y, ae.y, fmaf(x.z, ae.z, x.w * ae.w)));
        p = fmaf(y.x, ad.x, fmaf(y.y, ad.y, fmaf(y.z, ad.z, fmaf(y.w, ad.w, p))));
#pragma unroll
        for (int o = 16; o; o >>= 1) p += __shfl_xor_sync(0xffffffffu, p, o);
        if (lane == 0) {
            float v = base + g_sj[j] + p;
            sh[j] = v > 0.f ? v : ALPHA * v;
        }
    }
    __syncthreads();

    int4 a4 = ((const int4*)(adj + (size_t)i * NN))[tid];
    float4 v4 = *((float4*)&sh[tid * 4]);
    v4.x = a4.x > 0 ? v4.x : NEGV;
    v4.y = a4.y > 0 ? v4.y : NEGV;
    v4.z = a4.z > 0 ? v4.z : NEGV;
    v4.w = a4.w > 0 ? v4.w : NEGV;
    float m = fmaxf(fmaxf(v4.x, v4.y), fmaxf(v4.z, v4.w));
#pragma unroll
    for (int o = 16; o; o >>= 1) m = fmaxf(m, __shfl_xor_sync(0xffffffffu, m, o));
    if (lane == 0) red[warp] = m;
    __syncthreads();
    float mm = red[0];
#pragma unroll
    for (int k = 1; k < 8; k++) mm = fmaxf(mm, red[k]);

    float4 e4;
    e4.x = __expf(v4.x - mm);
    e4.y = __expf(v4.y - mm);
    e4.z = __expf(v4.z - mm);
    e4.w = __expf(v4.w - mm);
    ((float4*)(g_att + (size_t)i * NN))[tid] = e4;
    float s = (e4.x + e4.y) + (e4.z + e4.w);
#pragma unroll
    for (int o = 16; o; o >>= 1) s += __shfl_xor_sync(0xffffffffu, s, o);
    __syncthreads();
    if (lane == 0) red[warp] = s;
    __syncthreads();
    if (tid == 0) {
        float tot = red[0];
#pragma unroll
        for (int k = 1; k < 8; k++) tot += red[k];
        g_inv[i] = 1.f / tot;
    }
}

// ---------------------------------------------------------------------------
// Kernel D (REVERTED to v1 — the R10 known-good): out = elu((att*inv) @ Wh).
// 256 blocks x 256 threads, 4 rows/block.  v2's 8-row/128-block variant was
// latency-bound (<1 block/SM) and regressed ~+19us; occupancy beats traffic
// at this scale.  Attention rows staged TRANSPOSED in smem (inv folded in),
// inner loop = 1 broadcast LDS.128 + 1 coalesced LDG.128 + 16 FMA per j.
// ---------------------------------------------------------------------------
__global__ __launch_bounds__(256) void k_out(float* __restrict__ out) {
    int tid = threadIdx.x;
    int warp = tid >> 5, lane = tid & 31;
    int i0 = blockIdx.x * 4;

    __shared__ float4 attT[NN];        // attT[j] = {row0..row3} * inv  (16 KB)
    __shared__ float4 sred[4][8][32];  // cross-warp reduce              (16 KB)

    float iv0 = g_inv[i0 + 0], iv1 = g_inv[i0 + 1];
    float iv2 = g_inv[i0 + 2], iv3 = g_inv[i0 + 3];
    const float* att0 = g_att + (size_t)(i0 + 0) * NN;
    const float* att1 = g_att + (size_t)(i0 + 1) * NN;
    const float* att2 = g_att + (size_t)(i0 + 2) * NN;
    const float* att3 = g_att + (size_t)(i0 + 3) * NN;
#pragma unroll
    for (int q = 0; q < 4; q++) {
        int j = tid + q * 256;
        float4 v;
        v.x = att0[j] * iv0;
        v.y = att1[j] * iv1;
        v.z = att2[j] * iv2;
        v.w = att3[j] * iv3;
        attT[j] = v;                   // STS.128, lanes consecutive -> no conflict
    }
    __syncthreads();

    float4 c0 = make_float4(0.f, 0.f, 0.f, 0.f);
    float4 c1 = c0, c2 = c0, c3 = c0;
    const float4* wh4 = (const float4*)g_Wh;
    int jb = warp * 128;
#pragma unroll 4
    for (int jj = 0; jj < 128; jj++) {
        float4 a = attT[jb + jj];                       // broadcast
        float4 w = wh4[(size_t)(jb + jj) * 32 + lane];  // coalesced 512B/warp
        c0.x = fmaf(a.x, w.x, c0.x); c0.y = fmaf(a.x, w.y, c0.y);
        c0.z = fmaf(a.x, w.z, c0.z); c0.w = fmaf(a.x, w.w, c0.w);
        c1.x = fmaf(a.y, w.x, c1.x); c1.y = fmaf(a.y, w.y, c1.y);
        c1.z = fmaf(a.y, w.z, c1.z); c1.w = fmaf(a.y, w.w, c1.w);
        c2.x = fmaf(a.z, w.x, c2.x); c2.y = fmaf(a.z, w.y, c2.y);
        c2.z = fmaf(a.z, w.z, c2.z); c2.w = fmaf(a.z, w.w, c2.w);
        c3.x = fmaf(a.w, w.x, c3.x); c3.y = fmaf(a.w, w.y, c3.y);
        c3.z = fmaf(a.w, w.z, c3.z); c3.w = fmaf(a.w, w.w, c3.w);
    }
    sred[0][warp][lane] = c0;
    sred[1][warp][lane] = c1;
    sred[2][warp][lane] = c2;
    sred[3][warp][lane] = c3;
    __syncthreads();

    if (tid < 128) {
        int r = tid >> 5, c = tid & 31;
        float4 s = sred[r][0][c];
#pragma unroll
        for (int w = 1; w < 8; w++) {
            float4 o = sred[r][w][c];
            s.x += o.x; s.y += o.y; s.z += o.z; s.w += o.w;
        }
        float4 res;
        res.x = s.x > 0.f ? s.x : expm1f(s.x);
        res.y = s.y > 0.f ? s.y : expm1f(s.y);
        res.z = s.z > 0.f ? s.z : expm1f(s.z);
        res.w = s.w > 0.f ? s.w : expm1f(s.w);
        ((float4*)(out + (size_t)(i0 + r) * FF))[c] = res;
    }
}

// ---------------------------------------------------------------------------
// Launch.  Inputs: h, e_h, dialogue_embedding, adj, W_w, W_b, a_w, a_b.
// Output: fp32 [1024, 128].
// ---------------------------------------------------------------------------
extern "C" void kernel_launch(void* const* d_in, const int* in_sizes, int n_in,
                              void* d_out, int out_size) {
    const float* h   = (const float*)d_in[0];
    const float* eh  = (const float*)d_in[1];
    const float* de  = (const float*)d_in[2];
    const int*   adj = (const int*)d_in[3];
    const float* Ww  = (const float*)d_in[4];
    const float* Wb  = (const float*)d_in[5];
    const float* aw  = (const float*)d_in[6];
    const float* ab  = (const float*)d_in[7];
    float* out = (float*)d_out;

    k_wh<<<NN / 4, 256>>>(h, Ww, Wb, aw);
    k_attn<<<NN, 256>>>(eh, de, adj, aw, ab);
    k_out<<<NN / 4, 256>>>(out);
}

// round 17
// speedup vs baseline: 1.0877x; 1.0126x over previous
#include <cuda_runtime.h>

#define NN 1024
#define FF 128
#define ALPHA 0.2f
#define NEGV -9.0e15f

// Scratch (static device globals — no allocation)
__device__ float g_Wh[NN * FF];
__device__ float g_si[NN];
__device__ float g_sj[NN];
__device__ float g_inv[NN];
__device__ float g_att[(size_t)NN * NN];   // UNNORMALIZED exp weights

__device__ __forceinline__ float4 ldcs4(const float4* p) {
#if __CUDA_ARCH__ >= 800
    float4 v;
    asm volatile("ld.global.cs.v4.f32 {%0,%1,%2,%3}, [%4];"
                 : "=f"(v.x), "=f"(v.y), "=f"(v.z), "=f"(v.w) : "l"(p));
    return v;
#else
    return *p;
#endif
}

// ---------------------------------------------------------------------------
// Kernel A (v5): Wh = h @ W + b, fused s_i/s_j.
// 2 rows/block, 512 blocks x 256 threads, 8-way k-split:
//   warp w owns k in [16w, 16w+16); lane owns col quad [4*lane, 4*lane+4).
// vs v4: halves row-accum register pressure (56 -> ~40 regs) and doubles
// the grid (3.5 blocks/SM avg, ~6 resident possible) for issue overlap.
// W L2 traffic 32 MB (well under the LTS cap).
// ---------------------------------------------------------------------------
__global__ __launch_bounds__(256) void k_wh(const float* __restrict__ h,
                                            const float* __restrict__ W,
                                            const float* __restrict__ b,
                                            const float* __restrict__ aw) {
    int tid = threadIdx.x;
    int warp = tid >> 5, lane = tid & 31;
    int i0 = blockIdx.x * 2;

    __shared__ float hs[2][FF];             // 1 KB
    __shared__ float4 part[8][2][32];       // 8 KB: [kwarp][row][colquad]

    if (tid < 64)                           // 2 rows x 32 float4, coalesced
        ((float4*)hs)[tid] = ((const float4*)(h + (size_t)i0 * FF))[tid];
    __syncthreads();

    const float4* W4 = (const float4*)W;    // [128][32] float4
    float4 a0 = make_float4(0.f, 0.f, 0.f, 0.f);
    float4 a1 = a0;
    int k0 = warp * 16;
#pragma unroll
    for (int kk = 0; kk < 16; kk++) {
        int k = k0 + kk;
        float4 w = W4[k * 32 + lane];       // coalesced 512B/warp
        float h0 = hs[0][k], h1 = hs[1][k];
        a0.x = fmaf(h0, w.x, a0.x); a0.y = fmaf(h0, w.y, a0.y);
        a0.z = fmaf(h0, w.z, a0.z); a0.w = fmaf(h0, w.w, a0.w);
        a1.x = fmaf(h1, w.x, a1.x); a1.y = fmaf(h1, w.y, a1.y);
        a1.z = fmaf(h1, w.z, a1.z); a1.w = fmaf(h1, w.w, a1.w);
    }
    part[warp][0][lane] = a0;
    part[warp][1][lane] = a1;
    __syncthreads();

    if (tid < 64) {                         // warp r handles row i0+r
        int r = tid >> 5, l = tid & 31;
        float4 s = part[0][r][l];
#pragma unroll
        for (int w = 1; w < 8; w++) {
            float4 p = part[w][r][l];
            s.x += p.x; s.y += p.y; s.z += p.z; s.w += p.w;
        }
        float4 bb = ((const float4*)b)[l];
        s.x += bb.x; s.y += bb.y; s.z += bb.z; s.w += bb.w;
        ((float4*)(g_Wh + (size_t)(i0 + r) * FF))[l] = s;

        float4 ai = ((const float4*)aw)[l];
        float4 aj = ((const float4*)(aw + FF))[l];
        float pi = fmaf(s.x, ai.x, fmaf(s.y, ai.y, fmaf(s.z, ai.z, s.w * ai.w)));
        float pj = fmaf(s.x, aj.x, fmaf(s.y, aj.y, fmaf(s.z, aj.z, s.w * aj.w)));
#pragma unroll
        for (int o = 16; o; o >>= 1) {
            pi += __shfl_xor_sync(0xffffffffu, pi, o);
            pj += __shfl_xor_sync(0xffffffffu, pj, o);
        }
        if (l == 0) { g_si[i0 + r] = pi; g_sj[i0 + r] = pj; }
    }
}

// ---------------------------------------------------------------------------
// Kernel B (HBM-bound, PROTECTED WIN — byte-identical to R9/R10/R16): per
// row i, fused dual GEMV + leaky-ReLU + mask + softmax (unnormalized +
// g_inv).  __launch_bounds__(256,7) -> ALL 1024 blocks resident in ONE wave.
// ---------------------------------------------------------------------------
__global__ __launch_bounds__(256, 7) void k_attn(const float* __restrict__ eh,
                                                 const float* __restrict__ de,
                                                 const int* __restrict__ adj,
                                                 const float* __restrict__ aw,
                                                 const float* __restrict__ ab) {
    int i = blockIdx.x;
    int tid = threadIdx.x;
    int warp = tid >> 5, lane = tid & 31;

    __shared__ float sh[NN];
    __shared__ float red[8];

    float4 ae = ((const float4*)(aw + 2 * FF))[lane];
    float4 ad = ((const float4*)(aw + 3 * FF))[lane];
    float base = g_si[i] + ab[0];

    const float4* pe = (const float4*)(eh + (size_t)i * NN * FF);
    const float4* pd = (const float4*)(de + (size_t)i * NN * FF);

#pragma unroll 2
    for (int j = warp; j < NN; j += 8) {
        float4 x = ldcs4(pe + j * 32 + lane);
        float4 y = ldcs4(pd + j * 32 + lane);
        float p = fmaf(x.x, ae.x, fmaf(x.y, ae.y, fmaf(x.z, ae.z, x.w * ae.w)));
        p = fmaf(y.x, ad.x, fmaf(y.y, ad.y, fmaf(y.z, ad.z, fmaf(y.w, ad.w, p))));
#pragma unroll
        for (int o = 16; o; o >>= 1) p += __shfl_xor_sync(0xffffffffu, p, o);
        if (lane == 0) {
            float v = base + g_sj[j] + p;
            sh[j] = v > 0.f ? v : ALPHA * v;
        }
    }
    __syncthreads();

    int4 a4 = ((const int4*)(adj + (size_t)i * NN))[tid];
    float4 v4 = *((float4*)&sh[tid * 4]);
    v4.x = a4.x > 0 ? v4.x : NEGV;
    v4.y = a4.y > 0 ? v4.y : NEGV;
    v4.z = a4.z > 0 ? v4.z : NEGV;
    v4.w = a4.w > 0 ? v4.w : NEGV;
    float m = fmaxf(fmaxf(v4.x, v4.y), fmaxf(v4.z, v4.w));
#pragma unroll
    for (int o = 16; o; o >>= 1) m = fmaxf(m, __shfl_xor_sync(0xffffffffu, m, o));
    if (lane == 0) red[warp] = m;
    __syncthreads();
    float mm = red[0];
#pragma unroll
    for (int k = 1; k < 8; k++) mm = fmaxf(mm, red[k]);

    float4 e4;
    e4.x = __expf(v4.x - mm);
    e4.y = __expf(v4.y - mm);
    e4.z = __expf(v4.z - mm);
    e4.w = __expf(v4.w - mm);
    ((float4*)(g_att + (size_t)i * NN))[tid] = e4;
    float s = (e4.x + e4.y) + (e4.z + e4.w);
#pragma unroll
    for (int o = 16; o; o >>= 1) s += __shfl_xor_sync(0xffffffffu, s, o);
    __syncthreads();
    if (lane == 0) red[warp] = s;
    __syncthreads();
    if (tid == 0) {
        float tot = red[0];
#pragma unroll
        for (int k = 1; k < 8; k++) tot += red[k];
        g_inv[i] = 1.f / tot;
    }
}

// ---------------------------------------------------------------------------
// Kernel D (v1, PROTECTED — byte-identical to R10/R16): out =
// elu((att*inv) @ Wh).  256 blocks x 256 threads, 4 rows/block.
// Attention rows staged TRANSPOSED in smem (inv folded in), inner loop =
// 1 broadcast LDS.128 + 1 coalesced LDG.128 + 16 FMA per j.
// ---------------------------------------------------------------------------
__global__ __launch_bounds__(256) void k_out(float* __restrict__ out) {
    int tid = threadIdx.x;
    int warp = tid >> 5, lane = tid & 31;
    int i0 = blockIdx.x * 4;

    __shared__ float4 attT[NN];        // attT[j] = {row0..row3} * inv  (16 KB)
    __shared__ float4 sred[4][8][32];  // cross-warp reduce              (16 KB)

    float iv0 = g_inv[i0 + 0], iv1 = g_inv[i0 + 1];
    float iv2 = g_inv[i0 + 2], iv3 = g_inv[i0 + 3];
    const float* att0 = g_att + (size_t)(i0 + 0) * NN;
    const float* att1 = g_att + (size_t)(i0 + 1) * NN;
    const float* att2 = g_att + (size_t)(i0 + 2) * NN;
    const float* att3 = g_att + (size_t)(i0 + 3) * NN;
#pragma unroll
    for (int q = 0; q < 4; q++) {
        int j = tid + q * 256;
        float4 v;
        v.x = att0[j] * iv0;
        v.y = att1[j] * iv1;
        v.z = att2[j] * iv2;
        v.w = att3[j] * iv3;
        attT[j] = v;                   // STS.128, lanes consecutive -> no conflict
    }
    __syncthreads();

    float4 c0 = make_float4(0.f, 0.f, 0.f, 0.f);
    float4 c1 = c0, c2 = c0, c3 = c0;
    const float4* wh4 = (const float4*)g_Wh;
    int jb = warp * 128;
#pragma unroll 4
    for (int jj = 0; jj < 128; jj++) {
        float4 a = attT[jb + jj];                       // broadcast
        float4 w = wh4[(size_t)(jb + jj) * 32 + lane];  // coalesced 512B/warp
        c0.x = fmaf(a.x, w.x, c0.x); c0.y = fmaf(a.x, w.y, c0.y);
        c0.z = fmaf(a.x, w.z, c0.z); c0.w = fmaf(a.x, w.w, c0.w);
        c1.x = fmaf(a.y, w.x, c1.x); c1.y = fmaf(a.y, w.y, c1.y);
        c1.z = fmaf(a.y, w.z, c1.z); c1.w = fmaf(a.y, w.w, c1.w);
        c2.x = fmaf(a.z, w.x, c2.x); c2.y = fmaf(a.z, w.y, c2.y);
        c2.z = fmaf(a.z, w.z, c2.z); c2.w = fmaf(a.z, w.w, c2.w);
        c3.x = fmaf(a.w, w.x, c3.x); c3.y = fmaf(a.w, w.y, c3.y);
        c3.z = fmaf(a.w, w.z, c3.z); c3.w = fmaf(a.w, w.w, c3.w);
    }
    sred[0][warp][lane] = c0;
    sred[1][warp][lane] = c1;
    sred[2][warp][lane] = c2;
    sred[3][warp][lane] = c3;
    __syncthreads();

    if (tid < 128) {
        int r = tid >> 5, c = tid & 31;
        float4 s = sred[r][0][c];
#pragma unroll
        for (int w = 1; w < 8; w++) {
            float4 o = sred[r][w][c];
            s.x += o.x; s.y += o.y; s.z += o.z; s.w += o.w;
        }
        float4 res;
        res.x = s.x > 0.f ? s.x : expm1f(s.x);
        res.y = s.y > 0.f ? s.y : expm1f(s.y);
        res.z = s.z > 0.f ? s.z : expm1f(s.z);
        res.w = s.w > 0.f ? s.w : expm1f(s.w);
        ((float4*)(out + (size_t)(i0 + r) * FF))[c] = res;
    }
}

// ---------------------------------------------------------------------------
// Launch.  Inputs: h, e_h, dialogue_embedding, adj, W_w, W_b, a_w, a_b.
// Output: fp32 [1024, 128].
// ---------------------------------------------------------------------------
extern "C" void kernel_launch(void* const* d_in, const int* in_sizes, int n_in,
                              void* d_out, int out_size) {
    const float* h   = (const float*)d_in[0];
    const float* eh  = (const float*)d_in[1];
    const float* de  = (const float*)d_in[2];
    const int*   adj = (const int*)d_in[3];
    const float* Ww  = (const float*)d_in[4];
    const float* Wb  = (const float*)d_in[5];
    const float* aw  = (const float*)d_in[6];
    const float* ab  = (const float*)d_in[7];
    float* out = (float*)d_out;

    k_wh<<<NN / 2, 256>>>(h, Ww, Wb, aw);
    k_attn<<<NN, 256>>>(eh, de, adj, aw, ab);
    k_out<<<NN / 4, 256>>>(out);
}